// round 15
// baseline (speedup 1.0000x reference)
#include <cuda_runtime.h>

// Hamilton product of quaternions packed in the last dim (w, x, y, z).
// Shapes: q1, q2: (32, 4096, 64, 4) fp32 -> 8,388,608 quaternions.
//
// FINAL (converged, 15-round sweep). HBM-bound 2R+1W stream (~403 MB, zero
// reuse); every variant pins DRAM at 83-85% of the 8 TB/s spec — the B300
// achieved ceiling (LTS cap, path-independent). Deciding metric is harness
// graph-replay time, which consistently favors this shape:
//   QPT=1 / TPB=256 / plain float4:  {59.87, 60.29, 61.34} us  <- best
//   QPT=1 / TPB=128 or 512:          {61.47, 60.96} us
//   all ILP/v8-asm/persistent variants: 61.9-64.0 us
// One coalesced LDG.128 pair per thread (no front-batched MLP bursts) gives
// the smoothest L1tex-queue pressure across overlapping graph replays;
// isolated ncu kernel time rank-inverts with the bench here.

__global__ void __launch_bounds__(256) hamilton_kernel(
    const float4* __restrict__ q1,
    const float4* __restrict__ q2,
    float4* __restrict__ out,
    int n_quat)
{
    int i = blockIdx.x * blockDim.x + threadIdx.x;
    if (i >= n_quat) return;

    float4 a = q1[i];
    float4 b = q2[i];

    // a = (w1, x1, y1, z1), b = (w2, x2, y2, z2)
    float4 r;
    r.x = a.x * b.x - a.y * b.y - a.z * b.z - a.w * b.w;  // w
    r.y = a.x * b.y + a.y * b.x + a.z * b.w - a.w * b.z;  // x
    r.z = a.x * b.z - a.y * b.w + a.z * b.x + a.w * b.y;  // y
    r.w = a.x * b.w + a.y * b.z - a.z * b.y + a.w * b.x;  // z

    out[i] = r;
}

extern "C" void kernel_launch(void* const* d_in, const int* in_sizes, int n_in,
                              void* d_out, int out_size) {
    const float4* q1 = (const float4*)d_in[0];
    const float4* q2 = (const float4*)d_in[1];
    float4* out = (float4*)d_out;

    int n_quat = in_sizes[0] / 4;  // 8,388,608

    int threads = 256;
    int blocks = (n_quat + threads - 1) / threads;  // 32768
    hamilton_kernel<<<blocks, threads>>>(q1, q2, out, n_quat);
}

// round 16
// speedup vs baseline: 1.0111x; 1.0111x over previous
#include <cuda_runtime.h>

// Hamilton product of quaternions packed in the last dim (w, x, y, z).
// Shapes: q1, q2: (32, 4096, 64, 4) fp32 -> 8,388,608 quaternions.
//
// FINAL family (QPT=1 / TPB=256 / plain float4): best harness-replay times
// across the 16-round sweep ({59.87, 60.29, 61.18, 61.34} us vs 61.9-64.0
// for every ILP/v8/persistent variant). DRAM pinned at 83-85% of spec in
// all variants — the B300 achieved ceiling for a 2R+1W stream.
// R16 delta: n_quat % 256 == 0, so the main kernel drops the bounds guard
// (exact grid); a guarded tail kernel is kept for shape-generality but is
// never launched for this problem.

#define TPB 256

__device__ __forceinline__ float4 hprod(float4 a, float4 b) {
    float4 r;
    r.x = a.x * b.x - a.y * b.y - a.z * b.z - a.w * b.w;  // w
    r.y = a.x * b.y + a.y * b.x + a.z * b.w - a.w * b.z;  // x
    r.z = a.x * b.z - a.y * b.w + a.z * b.x + a.w * b.y;  // y
    r.w = a.x * b.w + a.y * b.z - a.z * b.y + a.w * b.x;  // z
    return r;
}

__global__ void __launch_bounds__(TPB) hamilton_kernel(
    const float4* __restrict__ q1,
    const float4* __restrict__ q2,
    float4* __restrict__ out)
{
    int i = blockIdx.x * TPB + threadIdx.x;
    out[i] = hprod(q1[i], q2[i]);
}

// Guarded tail for arbitrary n (not hit for this shape).
__global__ void __launch_bounds__(TPB) hamilton_kernel_tail(
    const float4* __restrict__ q1,
    const float4* __restrict__ q2,
    float4* __restrict__ out,
    int start, int n_quat)
{
    int i = start + blockIdx.x * TPB + threadIdx.x;
    if (i < n_quat) out[i] = hprod(q1[i], q2[i]);
}

extern "C" void kernel_launch(void* const* d_in, const int* in_sizes, int n_in,
                              void* d_out, int out_size) {
    const float4* q1 = (const float4*)d_in[0];
    const float4* q2 = (const float4*)d_in[1];
    float4* out = (float4*)d_out;

    int n_quat = in_sizes[0] / 4;      // 8,388,608
    int full_blocks = n_quat / TPB;    // 32768 (exact for this shape)
    int covered = full_blocks * TPB;

    if (full_blocks > 0)
        hamilton_kernel<<<full_blocks, TPB>>>(q1, q2, out);

    int rem = n_quat - covered;
    if (rem > 0) {
        int tail_blocks = (rem + TPB - 1) / TPB;
        hamilton_kernel_tail<<<tail_blocks, TPB>>>(q1, q2, out, covered, n_quat);
    }
}